// round 4
// baseline (speedup 1.0000x reference)
#include <cuda_runtime.h>
#include <cstdint>

// ---------------- problem constants ----------------
constexpr int S = 1024, B = 8, D = 1024, H = 16, F = 4096, E = 8;
constexpr int HD = D / H;           // 64
constexpr int N = S * B;            // 8192
constexpr int CAP = 4 * N / E;      // 4096

// ---------------- scratch (device globals; no allocations) ----------------
__device__ uint32_t g_xnh[N * D], g_xnl[N * D];      // LN1 out, tf32 hi/lo
__device__ float g_q  [N * D];
__device__ float g_k  [N * D];
__device__ float g_v  [N * D];
__device__ uint32_t g_aoh[N * D], g_aol[N * D];      // attn out, tf32 hi/lo
__device__ float g_x1 [N * D];
__device__ float g_tok[N * D];
__device__ uint32_t g_wqh[D * D], g_wql[D * D];
__device__ uint32_t g_wkh[D * D], g_wkl[D * D];
__device__ uint32_t g_wvh[D * D], g_wvl[D * D];
__device__ uint32_t g_woh[D * D], g_wol[D * D];
__device__ uint16_t g_dispb[E * CAP * D];            // bf16 dispatched tokens
__device__ uint16_t g_hb  [134217728];               // E*CAP*F bf16 hidden
__device__ float    g_eo  [E * CAP * D];
__device__ uint32_t g_w1p [(D / 2) * F * E];         // bf16 k-pair packed w1
__device__ uint32_t g_w2p [(F / 2) * D * E];         // bf16 k-pair packed w2
__device__ float g_gates[N * E];
__device__ int   g_eidx[N];
__device__ float g_gp  [N];
__device__ int   g_slot[N];
__device__ float g_gv  [N];
__device__ int   g_cnt [E];

// ---------------- helpers ----------------
__device__ __forceinline__ uint32_t f2tf32(float f) {
    uint32_t u;
    asm("cvt.rna.tf32.f32 %0, %1;" : "=r"(u) : "f"(f));
    return u;
}
// pack two fp32 into bf16x2 (memory order: first arg = low half)
__device__ __forceinline__ uint32_t packbf2(float lo, float hi) {
    uint32_t d;
    asm("cvt.rn.bf16x2.f32 %0, %1, %2;" : "=r"(d) : "f"(hi), "f"(lo));
    return d;
}

// ---------------- weight split: fp32 -> tf32 hi/lo ----------------
__global__ void __launch_bounds__(256) splitw_kernel(
    const float* __restrict__ W, uint32_t* __restrict__ Wh,
    uint32_t* __restrict__ Wl)
{
    int i = blockIdx.x * 256 + threadIdx.x;
    float v = W[i];
    uint32_t h = f2tf32(v);
    Wh[i] = h;
    Wl[i] = f2tf32(v - __uint_as_float(h));
}

// ---------------- LayerNorm (fp32 out) ----------------
__global__ void __launch_bounds__(256) ln_kernel(const float* __restrict__ x,
                                                 const float* __restrict__ gam,
                                                 const float* __restrict__ bet,
                                                 float* __restrict__ y) {
    int n = blockIdx.x;
    const float* row = x + (long)n * D;
    int t = threadIdx.x;
    float s = 0.f, s2 = 0.f;
    for (int d = t; d < D; d += 256) { float v = row[d]; s += v; s2 += v * v; }
    __shared__ float r1[256], r2[256];
    r1[t] = s; r2[t] = s2; __syncthreads();
    for (int st = 128; st > 0; st >>= 1) {
        if (t < st) { r1[t] += r1[t + st]; r2[t] += r2[t + st]; }
        __syncthreads();
    }
    float mean = r1[0] / D;
    float var  = r2[0] / D - mean * mean;
    float inv  = rsqrtf(var + 1e-5f);
    float* yo = y + (long)n * D;
    for (int d = t; d < D; d += 256)
        yo[d] = (row[d] - mean) * inv * gam[d] + bet[d];
}

// ---------------- LayerNorm (tf32 hi/lo out) ----------------
__global__ void __launch_bounds__(256) ln_split_kernel(
    const float* __restrict__ x, const float* __restrict__ gam,
    const float* __restrict__ bet,
    uint32_t* __restrict__ yh, uint32_t* __restrict__ yl)
{
    int n = blockIdx.x;
    const float* row = x + (long)n * D;
    int t = threadIdx.x;
    float s = 0.f, s2 = 0.f;
    for (int d = t; d < D; d += 256) { float v = row[d]; s += v; s2 += v * v; }
    __shared__ float r1[256], r2[256];
    r1[t] = s; r2[t] = s2; __syncthreads();
    for (int st = 128; st > 0; st >>= 1) {
        if (t < st) { r1[t] += r1[t + st]; r2[t] += r2[t + st]; }
        __syncthreads();
    }
    float mean = r1[0] / D;
    float var  = r2[0] / D - mean * mean;
    float inv  = rsqrtf(var + 1e-5f);
    for (int d = t; d < D; d += 256) {
        float v = (row[d] - mean) * inv * gam[d] + bet[d];
        uint32_t h = f2tf32(v);
        yh[(long)n * D + d] = h;
        yl[(long)n * D + d] = f2tf32(v - __uint_as_float(h));
    }
}

// ---------------- 3xTF32 GEMM, pre-split operands, double-buffered ----------
// C[M,Nc] = (Ah+Al)@(Bh+Bl) + bias) * scale (+ resid)
constexpr int T3_SMEM = 2 * 16 * 136 * 4 * 4;  // 69632 B dynamic

template<int HAS_RESID>
__global__ void __launch_bounds__(256) gemm_tf32x3p_kernel(
    const uint32_t* __restrict__ Ah, const uint32_t* __restrict__ Al,
    const uint32_t* __restrict__ Bh, const uint32_t* __restrict__ Bl,
    const float* __restrict__ bias, const float* __restrict__ resid,
    float* __restrict__ C, int M, int Nc, int K, float scale)
{
    extern __shared__ uint32_t dyn[];
    uint32_t* sAh = dyn;                 // [2][16][136]
    uint32_t* sAl = dyn + 2 * 2176;
    uint32_t* sBh = dyn + 4 * 2176;
    uint32_t* sBl = dyn + 6 * 2176;

    int t    = threadIdx.x;
    int wid  = t >> 5, lane = t & 31;
    int gid  = lane >> 2, tig = lane & 3;
    int wm0  = (wid & 1) * 64;
    int wn0  = (wid >> 1) * 32;
    int m0   = blockIdx.y * 128, n0 = blockIdx.x * 128;

    // staging coords
    int ar0 = (t * 2)      >> 2, ac0 = ((t * 2)      & 3) * 4;  // l=0
    int ar1 = (t * 2 + 1)  >> 2, ac1 = ((t * 2 + 1)  & 3) * 4;  // l=1 (same thread, 2 uint4)
    int br0 = t >> 5,        bc0 = (t & 31) * 4;
    int br1 = (t + 256) >> 5, bc1 = bc0;

    float acc[4][4][4];
#pragma unroll
    for (int mt = 0; mt < 4; mt++)
#pragma unroll
        for (int nt = 0; nt < 4; nt++)
#pragma unroll
            for (int r = 0; r < 4; r++) acc[mt][nt][r] = 0.f;

    const int nIter = K / 16;

    auto stage = [&](int buf, int k0,
                     uint4 vah0, uint4 vah1, uint4 val0, uint4 val1,
                     uint4 vbh0, uint4 vbh1, uint4 vbl0, uint4 vbl1) {
        uint32_t* ah = sAh + buf * 2176;
        uint32_t* al = sAl + buf * 2176;
        ah[(ac0 + 0) * 136 + ar0] = vah0.x; ah[(ac0 + 1) * 136 + ar0] = vah0.y;
        ah[(ac0 + 2) * 136 + ar0] = vah0.z; ah[(ac0 + 3) * 136 + ar0] = vah0.w;
        ah[(ac1 + 0) * 136 + ar1] = vah1.x; ah[(ac1 + 1) * 136 + ar1] = vah1.y;
        ah[(ac1 + 2) * 136 + ar1] = vah1.z; ah[(ac1 + 3) * 136 + ar1] = vah1.w;
        al[(ac0 + 0) * 136 + ar0] = val0.x; al[(ac0 + 1) * 136 + ar0] = val0.y;
        al[(ac0 + 2) * 136 + ar0] = val0.z; al[(ac0 + 3) * 136 + ar0] = val0.w;
        al[(ac1 + 0) * 136 + ar1] = val1.x; al[(ac1 + 1) * 136 + ar1] = val1.y;
        al[(ac1 + 2) * 136 + ar1] = val1.z; al[(ac1 + 3) * 136 + ar1] = val1.w;
        *(uint4*)&sBh[buf * 2176 + br0 * 136 + bc0] = vbh0;
        *(uint4*)&sBh[buf * 2176 + br1 * 136 + bc1] = vbh1;
        *(uint4*)&sBl[buf * 2176 + br0 * 136 + bc0] = vbl0;
        *(uint4*)&sBl[buf * 2176 + br1 * 136 + bc1] = vbl1;
    };
    auto loadA = [&](const uint32_t* P, int k0, int which) -> uint4 {
        int r = which ? ar1 : ar0, c = which ? ac1 : ac0;
        return *(const uint4*)(P + (long long)(m0 + r) * K + k0 + c);
    };
    auto loadB = [&](const uint32_t* P, int k0, int which) -> uint4 {
        int r = which ? br1 : br0, c = which ? bc1 : bc0;
        return *(const uint4*)(P + (long long)(k0 + r) * Nc + n0 + c);
    };

    {   // stage tile 0
        stage(0, 0,
              loadA(Ah, 0, 0), loadA(Ah, 0, 1), loadA(Al, 0, 0), loadA(Al, 0, 1),
              loadB(Bh, 0, 0), loadB(Bh, 0, 1), loadB(Bl, 0, 0), loadB(Bl, 0, 1));
    }
    __syncthreads();

    int cur = 0;
    for (int it = 0; it < nIter; ++it) {
        uint4 vah0, vah1, val0, val1, vbh0, vbh1, vbl0, vbl1;
        bool pf = (it + 1 < nIter);
        if (pf) {
            int k0 = (it + 1) * 16;
            vah0 = loadA(Ah, k0, 0); vah1 = loadA(Ah, k0, 1);
            val0 = loadA(Al, k0, 0); val1 = loadA(Al, k0, 1);
            vbh0 = loadB(Bh, k0, 0); vbh1 = loadB(Bh, k0, 1);
            vbl0 = loadB(Bl, k0, 0); vbl1 = loadB(Bl, k0, 1);
        }
        const uint32_t* ah = sAh + cur * 2176;
        const uint32_t* al = sAl + cur * 2176;
        const uint32_t* bh = sBh + cur * 2176;
        const uint32_t* bl = sBl + cur * 2176;
#pragma unroll
        for (int kb = 0; kb < 16; kb += 8) {
            uint32_t fah[4][4], fal[4][4], fbh[4][2], fbl[4][2];
#pragma unroll
            for (int mt = 0; mt < 4; mt++) {
                int mm = wm0 + mt * 16 + gid;
                fah[mt][0] = ah[(kb + tig    ) * 136 + mm];
                fah[mt][1] = ah[(kb + tig    ) * 136 + mm + 8];
                fah[mt][2] = ah[(kb + tig + 4) * 136 + mm];
                fah[mt][3] = ah[(kb + tig + 4) * 136 + mm + 8];
                fal[mt][0] = al[(kb + tig    ) * 136 + mm];
                fal[mt][1] = al[(kb + tig    ) * 136 + mm + 8];
                fal[mt][2] = al[(kb + tig + 4) * 136 + mm];
                fal[mt][3] = al[(kb + tig + 4) * 136 + mm + 8];
            }
#pragma unroll
            for (int nt = 0; nt < 4; nt++) {
                int nn = wn0 + nt * 8 + gid;
                fbh[nt][0] = bh[(kb + tig    ) * 136 + nn];
                fbh[nt][1] = bh[(kb + tig + 4) * 136 + nn];
                fbl[nt][0] = bl[(kb + tig    ) * 136 + nn];
                fbl[nt][1] = bl[(kb + tig + 4) * 136 + nn];
            }
#pragma unroll
            for (int mt = 0; mt < 4; mt++)
#pragma unroll
                for (int nt = 0; nt < 4; nt++) {
                    asm volatile(
                        "mma.sync.aligned.m16n8k8.row.col.f32.tf32.tf32.f32 "
                        "{%0,%1,%2,%3}, {%4,%5,%6,%7}, {%8,%9}, {%0,%1,%2,%3};"
                        : "+f"(acc[mt][nt][0]), "+f"(acc[mt][nt][1]),
                          "+f"(acc[mt][nt][2]), "+f"(acc[mt][nt][3])
                        : "r"(fah[mt][0]), "r"(fah[mt][1]), "r"(fah[mt][2]), "r"(fah[mt][3]),
                          "r"(fbl[nt][0]), "r"(fbl[nt][1]));
                    asm volatile(
                        "mma.sync.aligned.m16n8k8.row.col.f32.tf32.tf32.f32 "
                        "{%0,%1,%2,%3}, {%4,%5,%6,%7}, {%8,%9}, {%0,%1,%2,%3};"
                        : "+f"(acc[mt][nt][0]), "+f"(acc[mt][nt][1]),
                          "+f"(acc[mt][nt][2]), "+f"(acc[mt][nt][3])
                        : "r"(fal[mt][0]), "r"(fal[mt][1]), "r"(fal[mt][2]), "r"(fal[mt][3]),
                          "r"(fbh[nt][0]), "r"(fbh[nt][1]));
                    asm volatile(
                        "mma.sync.aligned.m16n8k8.row.col.f32.tf32.tf32.f32 "
                        "{%0,%1,%2,%3}, {%4,%5,%6,%7}, {%8,%9}, {%0,%1,%2,%3};"
                        : "+f"(acc[mt][nt][0]), "+f"(acc[mt][nt][1]),
                          "+f"(acc[mt][nt][2]), "+f"(acc[mt][nt][3])
                        : "r"(fah[mt][0]), "r"(fah[mt][1]), "r"(fah[mt][2]), "r"(fah[mt][3]),
                          "r"(fbh[nt][0]), "r"(fbh[nt][1]));
                }
        }
        if (pf)
            stage(cur ^ 1, 0, vah0, vah1, val0, val1, vbh0, vbh1, vbl0, vbl1);
        __syncthreads();
        cur ^= 1;
    }

#pragma unroll
    for (int mt = 0; mt < 4; mt++) {
#pragma unroll
        for (int nt = 0; nt < 4; nt++) {
            int row = m0 + wm0 + mt * 16 + gid;
            int col = n0 + wn0 + nt * 8 + 2 * tig;
            float b0 = bias[col], b1 = bias[col + 1];
            float c0 = (acc[mt][nt][0] + b0) * scale;
            float c1 = (acc[mt][nt][1] + b1) * scale;
            float c2 = (acc[mt][nt][2] + b0) * scale;
            float c3 = (acc[mt][nt][3] + b1) * scale;
            if (HAS_RESID) {
                float2 r0 = *(const float2*)(resid + (long long)row * Nc + col);
                float2 r1 = *(const float2*)(resid + (long long)(row + 8) * Nc + col);
                c0 += r0.x; c1 += r0.y; c2 += r1.x; c3 += r1.y;
            }
            *(float2*)(C + (long long)row * Nc + col)       = make_float2(c0, c1);
            *(float2*)(C + (long long)(row + 8) * Nc + col) = make_float2(c2, c3);
        }
    }
}

// ---------------- weight packing: fp32 [K][Nc] -> bf16 k-pair u32 [K/2][Nc] --
__global__ void __launch_bounds__(256) packw_kernel(
    const float* __restrict__ W, uint32_t* __restrict__ P, int Nc,
    long long sW, long long sP)
{
    int n  = blockIdx.x * 256 + threadIdx.x;
    int k2 = blockIdx.y;
    int z  = blockIdx.z;
    const float* w = W + (long long)z * sW + (long long)(2 * k2) * Nc + n;
    P[(long long)z * sP + (long long)k2 * Nc + n] = packbf2(w[0], w[Nc]);
}

// ---------------- bf16 tensor GEMM (experts; k32 tiles, double-buffered) ----
template<int RELU, int OUTBF>
__global__ void __launch_bounds__(256, 2) gemm_bf16_kernel(
    const uint16_t* __restrict__ A, const uint32_t* __restrict__ Bp,
    const float* __restrict__ bias, void* __restrict__ Cout,
    int M, int Nc, int K,
    long long sA, long long sB, long long sBias, long long sC)
{
    __shared__ uint32_t As2[2][16][136];
    __shared__ uint32_t Bs2[2][16][136];

    int z = blockIdx.z;
    A    += (long long)z * sA;
    Bp   += (long long)z * sB;
    bias += (long long)z * sBias;

    int t    = threadIdx.x;
    int wid  = t >> 5, lane = t & 31;
    int gid  = lane >> 2, tig = lane & 3;
    int wm0  = (wid & 1) * 64;
    int wn0  = (wid >> 1) * 32;
    int m0   = blockIdx.y * 128, n0 = blockIdx.x * 128;

    int am  = t & 127, ahh = t >> 7;        // A: row am, k-octet base ahh (+2 for l=1)
    int bk0 = t >> 5,  bn  = (t & 31) * 4;  // B pair-rows bk0 and bk0+8

    float acc[4][4][4];
#pragma unroll
    for (int mt = 0; mt < 4; mt++)
#pragma unroll
        for (int nt = 0; nt < 4; nt++)
#pragma unroll
            for (int r = 0; r < 4; r++) acc[mt][nt][r] = 0.f;

    const int nIter = K / 32;
    {   // stage tile 0
        uint4 va0 = *(const uint4*)(A + (long long)(m0 + am) * K + ahh * 8);
        uint4 va1 = *(const uint4*)(A + (long long)(m0 + am) * K + (ahh + 2) * 8);
        As2[0][ahh * 4 + 0][am] = va0.x; As2[0][ahh * 4 + 1][am] = va0.y;
        As2[0][ahh * 4 + 2][am] = va0.z; As2[0][ahh * 4 + 3][am] = va0.w;
        As2[0][(ahh + 2) * 4 + 0][am] = va1.x; As2[0][(ahh + 2) * 4 + 1][am] = va1.y;
        As2[0][(ahh + 2) * 4 + 2][am] = va1.z; As2[0][(ahh + 2) * 4 + 3][am] = va1.w;
        uint4 vb0 = *(const uint4*)(Bp + (long long)bk0 * Nc + n0 + bn);
        uint4 vb1 = *(const uint4*)(Bp + (long long)(bk0 + 8) * Nc + n0 + bn);
        *(uint4*)&Bs2[0][bk0][bn]     = vb0;
        *(uint4*)&Bs2[0][bk0 + 8][bn] = vb1;
    }
    __syncthreads();

    int cur = 0;
    for (int it = 0; it < nIter; ++it) {
        uint4 va0, va1, vb0, vb1;
        bool pf = (it + 1 < nIter);
        if (pf) {
            long long ka = (long long)(m0 + am) * K + (it + 1) * 32;
            va0 = *(const uint4*)(A + ka + ahh * 8);
            va1 = *(const uint4*)(A + ka + (ahh + 2) * 8);
            long long kb = (long long)((it + 1) * 16);
            vb0 = *(const uint4*)(Bp + (kb + bk0) * Nc + n0 + bn);
            vb1 = *(const uint4*)(Bp + (kb + bk0 + 8) * Nc + n0 + bn);
        }
#pragma unroll
        for (int kb2 = 0; kb2 < 2; kb2++) {
            int ko = kb2 * 8;
            uint32_t af[4][4], bfr[4][2];
#pragma unroll
            for (int mt = 0; mt < 4; mt++) {
                int mm = wm0 + mt * 16 + gid;
                af[mt][0] = As2[cur][ko + tig    ][mm];
                af[mt][1] = As2[cur][ko + tig    ][mm + 8];
                af[mt][2] = As2[cur][ko + tig + 4][mm];
                af[mt][3] = As2[cur][ko + tig + 4][mm + 8];
            }
#pragma unroll
            for (int nt = 0; nt < 4; nt++) {
                int nn = wn0 + nt * 8 + gid;
                bfr[nt][0] = Bs2[cur][ko + tig    ][nn];
                bfr[nt][1] = Bs2[cur][ko + tig + 4][nn];
            }
#pragma unroll
            for (int mt = 0; mt < 4; mt++)
#pragma unroll
                for (int nt = 0; nt < 4; nt++) {
                    asm volatile(
                        "mma.sync.aligned.m16n8k16.row.col.f32.bf16.bf16.f32 "
                        "{%0,%1,%2,%3}, {%4,%5,%6,%7}, {%8,%9}, {%0,%1,%2,%3};"
                        : "+f"(acc[mt][nt][0]), "+f"(acc[mt][nt][1]),
                          "+f"(acc[mt][nt][2]), "+f"(acc[mt][nt][3])
                        : "r"(af[mt][0]), "r"(af[mt][1]),
                          "r"(af[mt][2]), "r"(af[mt][3]),
                          "r"(bfr[nt][0]), "r"(bfr[nt][1]));
                }
        }
        if (pf) {
            int nx = cur ^ 1;
            As2[nx][ahh * 4 + 0][am] = va0.x; As2[nx][ahh * 4 + 1][am] = va0.y;
            As2[nx][ahh * 4 + 2][am] = va0.z; As2[nx][ahh * 4 + 3][am] = va0.w;
            As2[nx][(ahh + 2) * 4 + 0][am] = va1.x; As2[nx][(ahh + 2) * 4 + 1][am] = va1.y;
            As2[nx][(ahh + 2) * 4 + 2][am] = va1.z; As2[nx][(ahh + 2) * 4 + 3][am] = va1.w;
            *(uint4*)&Bs2[nx][bk0][bn]     = vb0;
            *(uint4*)&Bs2[nx][bk0 + 8][bn] = vb1;
        }
        __syncthreads();
        cur ^= 1;
    }

#pragma unroll
    for (int mt = 0; mt < 4; mt++) {
#pragma unroll
        for (int nt = 0; nt < 4; nt++) {
            int row = m0 + wm0 + mt * 16 + gid;
            int col = n0 + wn0 + nt * 8 + 2 * tig;
            float b0 = bias[col], b1 = bias[col + 1];
            float c0 = acc[mt][nt][0] + b0;
            float c1 = acc[mt][nt][1] + b1;
            float c2 = acc[mt][nt][2] + b0;
            float c3 = acc[mt][nt][3] + b1;
            if (RELU) {
                c0 = fmaxf(c0, 0.f); c1 = fmaxf(c1, 0.f);
                c2 = fmaxf(c2, 0.f); c3 = fmaxf(c3, 0.f);
            }
            if (OUTBF) {
                uint16_t* Cb = (uint16_t*)Cout + (long long)z * sC;
                *(uint32_t*)(Cb + (long long)row * Nc + col)       = packbf2(c0, c1);
                *(uint32_t*)(Cb + (long long)(row + 8) * Nc + col) = packbf2(c2, c3);
            } else {
                float* Cf = (float*)Cout + (long long)z * sC;
                *(float2*)(Cf + (long long)row * Nc + col)       = make_float2(c0, c1);
                *(float2*)(Cf + (long long)(row + 8) * Nc + col) = make_float2(c2, c3);
            }
        }
    }
}

// ---------------- flash attention (fp32, causal; emits tf32 hi/lo) ----------
constexpr int QT = 128, KT = 64;
constexpr int ATTN_SMEM = (QT * (HD + 1) + 2 * KT * HD) * 4;  // 66048 B

__global__ void __launch_bounds__(128) attn_kernel(
    const float* __restrict__ Q, const float* __restrict__ Kg,
    const float* __restrict__ Vg,
    uint32_t* __restrict__ Oh, uint32_t* __restrict__ Ol)
{
    extern __shared__ float sm[];
    float* q_s = sm;
    float* k_s = sm + QT * (HD + 1);
    float* v_s = k_s + KT * HD;

    int bh = blockIdx.y;
    int h  = bh % H, b = bh / H;
    int q0 = blockIdx.x * QT;
    int t  = threadIdx.x;
    long base = (long)b * D + (long)h * HD;

    for (int f = t; f < QT * HD / 4; f += 128) {
        int r  = f / (HD / 4);
        int c4 = (f % (HD / 4)) * 4;
        float4 v = *(const float4*)(Q + (long)(q0 + r) * (B * D) + base + c4);
        q_s[r * (HD + 1) + c4 + 0] = v.x;
        q_s[r * (HD + 1) + c4 + 1] = v.y;
        q_s[r * (HD + 1) + c4 + 2] = v.z;
        q_s[r * (HD + 1) + c4 + 3] = v.w;
    }
    __syncthreads();

    int sq = q0 + t;
    float m_run = -1e30f, l_run = 0.f;
    float acc[HD];
#pragma unroll
    for (int d = 0; d < HD; d++) acc[d] = 0.f;

    int kend = q0 + QT;
    for (int k0 = 0; k0 < kend; k0 += KT) {
        for (int f = t; f < KT * HD / 4; f += 128) {
            int r  = f / (HD / 4);
            int c4 = (f % (HD / 4)) * 4;
            *(float4*)(&k_s[r * HD + c4]) =
                *(const float4*)(Kg + (long)(k0 + r) * (B * D) + base + c4);
            *(float4*)(&v_s[r * HD + c4]) =
                *(const float4*)(Vg + (long)(k0 + r) * (B * D) + base + c4);
        }
        __syncthreads();

        float s[KT];
#pragma unroll
        for (int j = 0; j < KT; j++) s[j] = 0.f;
        for (int d = 0; d < HD; d++) {
            float qd = q_s[t * (HD + 1) + d];
#pragma unroll
            for (int j = 0; j < KT; j++) s[j] += qd * k_s[j * HD + d];
        }
        float mnew = m_run;
#pragma unroll
        for (int j = 0; j < KT; j++) {
            if (k0 + j > sq) s[j] = -1e9f;
            mnew = fmaxf(mnew, s[j]);
        }
        float corr = __expf(m_run - mnew);
        l_run *= corr;
#pragma unroll
        for (int d = 0; d < HD; d++) acc[d] *= corr;
        for (int j = 0; j < KT; j++) {
            float p = __expf(s[j] - mnew);
            l_run += p;
#pragma unroll
            for (int d = 0; d < HD; d++) acc[d] += p * v_s[j * HD + d];
        }
        m_run = mnew;
        __syncthreads();
    }
    float inv = 1.f / l_run;
    long off = (long)sq * (B * D) + base;
#pragma unroll
    for (int d = 0; d < HD; d++) {
        float v = acc[d] * inv;
        uint32_t hi = f2tf32(v);
        Oh[off + d] = hi;
        Ol[off + d] = f2tf32(v - __uint_as_float(hi));
    }
}

// ---------------- gate: logits, softmax, argmax (fp32, exact) ----------------
__global__ void __launch_bounds__(256) gate_kernel(
    const float* __restrict__ tok, const float* __restrict__ gw,
    float* __restrict__ gates, int* __restrict__ eidx, float* __restrict__ gp)
{
    int n = blockIdx.x, t = threadIdx.x;
    const float* row = tok + (long)n * D;
    float p[E];
#pragma unroll
    for (int e = 0; e < E; e++) p[e] = 0.f;
    for (int d = t; d < D; d += 256) {
        float xv = row[d];
        const float* w = gw + (long)d * E;
#pragma unroll
        for (int e = 0; e < E; e++) p[e] += xv * w[e];
    }
    __shared__ float red[256 * E];
#pragma unroll
    for (int e = 0; e < E; e++) red[t * E + e] = p[e];
    __syncthreads();
    for (int st = 128; st > 0; st >>= 1) {
        if (t < st)
#pragma unroll
            for (int e = 0; e < E; e++) red[t * E + e] += red[(t + st) * E + e];
        __syncthreads();
    }
    if (t == 0) {
        float lg[E], mx = -1e30f;
#pragma unroll
        for (int e = 0; e < E; e++) { lg[e] = red[e]; mx = fmaxf(mx, lg[e]); }
        float sum = 0.f, pr[E];
#pragma unroll
        for (int e = 0; e < E; e++) { pr[e] = __expf(lg[e] - mx); sum += pr[e]; }
        float inv = 1.f / sum;
        int best = 0; float bv = -1e30f;
#pragma unroll
        for (int e = 0; e < E; e++) {
            float g = pr[e] * inv;
            gates[(long)n * E + e] = g;
            if (g > bv) { bv = g; best = e; }
        }
        eidx[n] = best;
        gp[n]   = bv;
    }
}

// ---------------- routing scan (deterministic, single block) ----------------
__global__ void __launch_bounds__(256) scan_kernel(
    const int* __restrict__ eidx, const float* __restrict__ gp,
    int* __restrict__ slot, float* __restrict__ gv, int* __restrict__ cnt)
{
    __shared__ int scnt[256][E];
    int t = threadIdx.x;
    int c[E];
#pragma unroll
    for (int e = 0; e < E; e++) c[e] = 0;
    int n0 = t * (N / 256);
    for (int i = 0; i < N / 256; i++) c[eidx[n0 + i]]++;
#pragma unroll
    for (int e = 0; e < E; e++) scnt[t][e] = c[e];
    __syncthreads();
    if (t < E) {
        int run = 0;
        for (int j = 0; j < 256; j++) { int tmp = scnt[j][t]; scnt[j][t] = run; run += tmp; }
        cnt[t] = run;
    }
    __syncthreads();
    int off[E];
#pragma unroll
    for (int e = 0; e < E; e++) off[e] = scnt[t][e];
    for (int i = 0; i < N / 256; i++) {
        int n = n0 + i;
        int e = eidx[n];
        int l = off[e]++;
        bool keep = (l < CAP);
        slot[n] = keep ? e * CAP + l : -1;
        gv[n]   = keep ? gp[n] : 0.f;
    }
}

// ---------------- l_aux (deterministic tree reduce) ----------------
__global__ void __launch_bounds__(256) laux_kernel(
    const float* __restrict__ gates, const int* __restrict__ cnt,
    float* __restrict__ out_laux)
{
    __shared__ float red[256];
    int t = threadIdx.x;
    float loc[E];
#pragma unroll
    for (int e = 0; e < E; e++) loc[e] = 0.f;
    for (int n = t; n < N; n += 256)
#pragma unroll
        for (int e = 0; e < E; e++) loc[e] += gates[(long)n * E + e];
    float total[E];
    for (int e = 0; e < E; e++) {
        red[t] = loc[e]; __syncthreads();
        for (int st = 128; st > 0; st >>= 1) {
            if (t < st) red[t] += red[t + st];
            __syncthreads();
        }
        if (t == 0) total[e] = red[0];
        __syncthreads();
    }
    if (t == 0) {
        float la = 0.f;
        for (int e = 0; e < E; e++)
            la += (total[e] / N) * ((float)cnt[e] / N);
        *out_laux = (float)E * la;
    }
}

// ---------------- dispatch / combine ----------------
__global__ void __launch_bounds__(256) dispatch_kernel(
    const float* __restrict__ tok, const int* __restrict__ slot,
    uint16_t* __restrict__ dispb)
{
    int n = blockIdx.x;
    int s = slot[n];
    if (s < 0) return;
    int t = threadIdx.x;
    float4 v = ((const float4*)(tok + (long)n * D))[t];
    uint2 o;
    o.x = packbf2(v.x, v.y);
    o.y = packbf2(v.z, v.w);
    *(uint2*)(dispb + (long)s * D + t * 4) = o;
}

__global__ void __launch_bounds__(256) combine_kernel(
    const float* __restrict__ x1, const float* __restrict__ eo,
    const int* __restrict__ slot, const float* __restrict__ gv,
    float* __restrict__ out)
{
    int n = blockIdx.x, t = threadIdx.x;
    int s = slot[n];
    float g = gv[n];
    float4 r = ((const float4*)(x1 + (long)n * D))[t];
    if (s >= 0) {
        float4 v = ((const float4*)(eo + (long)s * D))[t];
        r.x += v.x * g; r.y += v.y * g; r.z += v.z * g; r.w += v.w * g;
    }
    ((float4*)(out + (long)n * D))[t] = r;
}

// ---------------- launch ----------------
extern "C" void kernel_launch(void* const* d_in, const int* in_sizes, int n_in,
                              void* d_out, int out_size) {
    const float* x    = (const float*)d_in[0];
    const float* wq   = (const float*)d_in[2];
    const float* bq   = (const float*)d_in[3];
    const float* wk   = (const float*)d_in[4];
    const float* bk   = (const float*)d_in[5];
    const float* wv   = (const float*)d_in[6];
    const float* bv   = (const float*)d_in[7];
    const float* wo   = (const float*)d_in[8];
    const float* bo   = (const float*)d_in[9];
    const float* ln1g = (const float*)d_in[10];
    const float* ln1b = (const float*)d_in[11];
    const float* ln2g = (const float*)d_in[12];
    const float* ln2b = (const float*)d_in[13];
    const float* gw   = (const float*)d_in[14];
    const float* w1   = (const float*)d_in[15];
    const float* b1   = (const float*)d_in[16];
    const float* w2   = (const float*)d_in[17];
    const float* b2   = (const float*)d_in[18];
    float* out = (float*)d_out;

    float *q, *k, *v, *x1, *tok, *eo, *gates, *gp, *gv;
    uint32_t *xnh, *xnl, *aoh, *aol;
    uint32_t *wqh, *wql, *wkh, *wkl, *wvh, *wvl, *woh, *wol;
    uint16_t *dispb, *hb;
    uint32_t *w1p, *w2p;
    int *eidx, *slot, *cnt;
    cudaGetSymbolAddress((void**)&xnh,   g_xnh);
    cudaGetSymbolAddress((void**)&xnl,   g_xnl);
    cudaGetSymbolAddress((void**)&q,     g_q);
    cudaGetSymbolAddress((void**)&k,     g_k);
    cudaGetSymbolAddress((void**)&v,     g_v);
    cudaGetSymbolAddress((void**)&aoh,   g_aoh);
    cudaGetSymbolAddress((void**)&aol,   g_aol);
    cudaGetSymbolAddress((void**)&x1,    g_x1);
    cudaGetSymbolAddress((void**)&tok,   g_tok);
    cudaGetSymbolAddress((void**)&wqh,   g_wqh);
    cudaGetSymbolAddress((void**)&wql,   g_wql);
    cudaGetSymbolAddress((void**)&wkh,   g_wkh);
    cudaGetSymbolAddress((void**)&wkl,   g_wkl);
    cudaGetSymbolAddress((void**)&wvh,   g_wvh);
    cudaGetSymbolAddress((void**)&wvl,   g_wvl);
    cudaGetSymbolAddress((void**)&woh,   g_woh);
    cudaGetSymbolAddress((void**)&wol,   g_wol);
    cudaGetSymbolAddress((void**)&dispb, g_dispb);
    cudaGetSymbolAddress((void**)&hb,    g_hb);
    cudaGetSymbolAddress((void**)&eo,    g_eo);
    cudaGetSymbolAddress((void**)&w1p,   g_w1p);
    cudaGetSymbolAddress((void**)&w2p,   g_w2p);
    cudaGetSymbolAddress((void**)&gates, g_gates);
    cudaGetSymbolAddress((void**)&gp,    g_gp);
    cudaGetSymbolAddress((void**)&gv,    g_gv);
    cudaGetSymbolAddress((void**)&eidx,  g_eidx);
    cudaGetSymbolAddress((void**)&slot,  g_slot);
    cudaGetSymbolAddress((void**)&cnt,   g_cnt);

    cudaFuncSetAttribute(attn_kernel,
                         cudaFuncAttributeMaxDynamicSharedMemorySize, ATTN_SMEM);
    cudaFuncSetAttribute(gemm_tf32x3p_kernel<0>,
                         cudaFuncAttributeMaxDynamicSharedMemorySize, T3_SMEM);
    cudaFuncSetAttribute(gemm_tf32x3p_kernel<1>,
                         cudaFuncAttributeMaxDynamicSharedMemorySize, T3_SMEM);

    const float qscale = 0.125f;  // HD^-0.5

    // one-time prep: weight splits / packs (independent)
    splitw_kernel<<<D * D / 256, 256>>>(wq, wqh, wql);
    splitw_kernel<<<D * D / 256, 256>>>(wk, wkh, wkl);
    splitw_kernel<<<D * D / 256, 256>>>(wv, wvh, wvl);
    splitw_kernel<<<D * D / 256, 256>>>(wo, woh, wol);
    packw_kernel<<<dim3(F / 256, D / 2, E), 256>>>(w1, w1p, F,
        (long long)D * F, (long long)(D / 2) * F);
    packw_kernel<<<dim3(D / 256, F / 2, E), 256>>>(w2, w2p, D,
        (long long)F * D, (long long)(F / 2) * D);

    // 1) LN1 -> tf32 hi/lo
    ln_split_kernel<<<N, 256>>>(x, ln1g, ln1b, xnh, xnl);
    // 2) Q/K/V projections (3xTF32, pre-split, double-buffered)
    gemm_tf32x3p_kernel<0><<<dim3(D / 128, N / 128), 256, T3_SMEM>>>(
        xnh, xnl, wqh, wql, bq, nullptr, q, N, D, D, qscale);
    gemm_tf32x3p_kernel<0><<<dim3(D / 128, N / 128), 256, T3_SMEM>>>(
        xnh, xnl, wkh, wkl, bk, nullptr, k, N, D, D, 1.f);
    gemm_tf32x3p_kernel<0><<<dim3(D / 128, N / 128), 256, T3_SMEM>>>(
        xnh, xnl, wvh, wvl, bv, nullptr, v, N, D, D, 1.f);
    // 3) attention (fp32 math; splits its output)
    attn_kernel<<<dim3(S / QT, B * H), 128, ATTN_SMEM>>>(q, k, v, aoh, aol);
    // 4) output projection + residual
    gemm_tf32x3p_kernel<1><<<dim3(D / 128, N / 128), 256, T3_SMEM>>>(
        aoh, aol, woh, wol, bo, x, x1, N, D, D, 1.f);
    // 5) LN2 (fp32 out, feeds gate + dispatch)
    ln_kernel<<<N, 256>>>(x1, ln2g, ln2b, tok);
    // 6) gate
    gate_kernel<<<N, 256>>>(tok, gw, gates, eidx, gp);
    // 7) routing scan
    scan_kernel<<<1, 256>>>(eidx, gp, slot, gv, cnt);
    // 8) l_aux -> last output element
    laux_kernel<<<1, 256>>>(gates, cnt, out + (out_size - 1));
    // 9) dispatch (writes bf16)
    dispatch_kernel<<<N, 256>>>(tok, slot, dispb);
    // 10) expert GEMM1 (relu, bf16 in, bf16 out)
    gemm_bf16_kernel<1, 1><<<dim3(F / 128, CAP / 128, E), 256>>>(
        dispb, w1p, b1, hb, CAP, F, D,
        (long long)CAP * D, (long long)(D / 2) * F, (long long)F, (long long)CAP * F);
    // 11) expert GEMM2 (bf16 in, fp32 out)
    gemm_bf16_kernel<0, 0><<<dim3(D / 128, CAP / 128, E), 256>>>(
        hb, w2p, b2, eo, CAP, D, F,
        (long long)CAP * F, (long long)(F / 2) * D, (long long)D, (long long)CAP * D);
    // 12) combine + residual -> output
    combine_kernel<<<N, 256>>>(x1, eo, slot, gv, out);
}

// round 6
// speedup vs baseline: 1.0094x; 1.0094x over previous
#include <cuda_runtime.h>
#include <cstdint>

// ---------------- problem constants ----------------
constexpr int S = 1024, B = 8, D = 1024, H = 16, F = 4096, E = 8;
constexpr int HD = D / H;           // 64
constexpr int N = S * B;            // 8192
constexpr int CAP = 4 * N / E;      // 4096
constexpr int D3 = 3 * D;           // 3072 (merged qkv width)

// ---------------- scratch (device globals; no allocations) ----------------
__device__ uint32_t g_xnh[N * D], g_xnl[N * D];      // LN1 out, tf32 hi/lo
__device__ float    g_qkv[N * D3];                   // merged q|k|v
__device__ uint32_t g_aoh[N * D], g_aol[N * D];      // attn out, tf32 hi/lo
__device__ float g_x1 [N * D];
__device__ float g_tok[N * D];
__device__ uint32_t g_wqkvh[D * D3], g_wqkvl[D * D3];
__device__ float    g_b3[D3];
__device__ uint32_t g_woh[D * D], g_wol[D * D];
__device__ uint16_t g_dispb[E * CAP * D];            // bf16 dispatched tokens
__device__ uint16_t g_hb  [134217728];               // E*CAP*F bf16 hidden
__device__ float    g_eo  [E * CAP * D];
__device__ uint32_t g_w1p [(D / 2) * F * E];         // bf16 k-pair packed w1
__device__ uint32_t g_w2p [(F / 2) * D * E];         // bf16 k-pair packed w2
__device__ float g_gates[N * E];
__device__ int   g_eidx[N];
__device__ float g_gp  [N];
__device__ int   g_slot[N];
__device__ float g_gv  [N];
__device__ int   g_cnt [E];

// ---------------- helpers ----------------
__device__ __forceinline__ uint32_t f2tf32(float f) {
    uint32_t u;
    asm("cvt.rna.tf32.f32 %0, %1;" : "=r"(u) : "f"(f));
    return u;
}
__device__ __forceinline__ uint32_t packbf2(float lo, float hi) {
    uint32_t d;
    asm("cvt.rn.bf16x2.f32 %0, %1, %2;" : "=r"(d) : "f"(hi), "f"(lo));
    return d;
}

// ---------------- weight split (with column offset + exact pow2 scale) ------
__global__ void __launch_bounds__(256) splitw3_kernel(
    const float* __restrict__ W, uint32_t* __restrict__ Wh3,
    uint32_t* __restrict__ Wl3, int colOff, float scale)
{
    int i = blockIdx.x * 256 + threadIdx.x;   // over D*D
    int d = i >> 10, e = i & 1023;
    float v = W[i] * scale;                   // scale is power of 2: exact
    uint32_t h = f2tf32(v);
    Wh3[(long long)d * D3 + colOff + e] = h;
    Wl3[(long long)d * D3 + colOff + e] = f2tf32(v - __uint_as_float(h));
}
__global__ void __launch_bounds__(256) splitw_kernel(
    const float* __restrict__ W, uint32_t* __restrict__ Wh,
    uint32_t* __restrict__ Wl)
{
    int i = blockIdx.x * 256 + threadIdx.x;
    float v = W[i];
    uint32_t h = f2tf32(v);
    Wh[i] = h;
    Wl[i] = f2tf32(v - __uint_as_float(h));
}
__global__ void __launch_bounds__(256) biascat_kernel(
    const float* __restrict__ src, float* __restrict__ dst, float scale)
{
    int i = blockIdx.x * 256 + threadIdx.x;
    dst[i] = src[i] * scale;
}

// ---------------- LayerNorm (fp32 out) ----------------
__global__ void __launch_bounds__(256) ln_kernel(const float* __restrict__ x,
                                                 const float* __restrict__ gam,
                                                 const float* __restrict__ bet,
                                                 float* __restrict__ y) {
    int n = blockIdx.x;
    const float* row = x + (long)n * D;
    int t = threadIdx.x;
    float s = 0.f, s2 = 0.f;
    for (int d = t; d < D; d += 256) { float v = row[d]; s += v; s2 += v * v; }
    __shared__ float r1[256], r2[256];
    r1[t] = s; r2[t] = s2; __syncthreads();
    for (int st = 128; st > 0; st >>= 1) {
        if (t < st) { r1[t] += r1[t + st]; r2[t] += r2[t + st]; }
        __syncthreads();
    }
    float mean = r1[0] / D;
    float var  = r2[0] / D - mean * mean;
    float inv  = rsqrtf(var + 1e-5f);
    float* yo = y + (long)n * D;
    for (int d = t; d < D; d += 256)
        yo[d] = (row[d] - mean) * inv * gam[d] + bet[d];
}

// ---------------- LayerNorm (tf32 hi/lo out) ----------------
__global__ void __launch_bounds__(256) ln_split_kernel(
    const float* __restrict__ x, const float* __restrict__ gam,
    const float* __restrict__ bet,
    uint32_t* __restrict__ yh, uint32_t* __restrict__ yl)
{
    int n = blockIdx.x;
    const float* row = x + (long)n * D;
    int t = threadIdx.x;
    float s = 0.f, s2 = 0.f;
    for (int d = t; d < D; d += 256) { float v = row[d]; s += v; s2 += v * v; }
    __shared__ float r1[256], r2[256];
    r1[t] = s; r2[t] = s2; __syncthreads();
    for (int st = 128; st > 0; st >>= 1) {
        if (t < st) { r1[t] += r1[t + st]; r2[t] += r2[t + st]; }
        __syncthreads();
    }
    float mean = r1[0] / D;
    float var  = r2[0] / D - mean * mean;
    float inv  = rsqrtf(var + 1e-5f);
    for (int d = t; d < D; d += 256) {
        float v = (row[d] - mean) * inv * gam[d] + bet[d];
        uint32_t h = f2tf32(v);
        yh[(long)n * D + d] = h;
        yl[(long)n * D + d] = f2tf32(v - __uint_as_float(h));
    }
}

// ---------------- 3xTF32 GEMM, pre-split, single-buffer, occ=2 --------------
// C[M,Nc] = (Ah+Al)@(Bh+Bl) + bias (+ resid). Block 128x128, warp 64x32.
template<int HAS_RESID>
__global__ void __launch_bounds__(256, 2) gemm_t3s_kernel(
    const uint32_t* __restrict__ Ah, const uint32_t* __restrict__ Al,
    const uint32_t* __restrict__ Bh, const uint32_t* __restrict__ Bl,
    const float* __restrict__ bias, const float* __restrict__ resid,
    float* __restrict__ C, int M, int Nc, int K)
{
    __shared__ uint32_t As_h[16][136], As_l[16][136];
    __shared__ uint32_t Bs_h[16][136], Bs_l[16][136];

    int t    = threadIdx.x;
    int wid  = t >> 5, lane = t & 31;
    int gid  = lane >> 2, tig = lane & 3;
    int wm0  = (wid & 1) * 64;
    int wn0  = (wid >> 1) * 32;
    int m0   = blockIdx.y * 128, n0 = blockIdx.x * 128;

    float acc[4][4][4];
#pragma unroll
    for (int mt = 0; mt < 4; mt++)
#pragma unroll
        for (int nt = 0; nt < 4; nt++)
#pragma unroll
            for (int r = 0; r < 4; r++) acc[mt][nt][r] = 0.f;

    for (int k0 = 0; k0 < K; k0 += 16) {
#pragma unroll
        for (int l = 0; l < 2; l++) {
            int f  = t + l * 256;
            int r  = f >> 2;
            int c4 = (f & 3) * 4;
            uint4 vh = *(const uint4*)(Ah + (long long)(m0 + r) * K + k0 + c4);
            uint4 vl = *(const uint4*)(Al + (long long)(m0 + r) * K + k0 + c4);
            As_h[c4 + 0][r] = vh.x; As_h[c4 + 1][r] = vh.y;
            As_h[c4 + 2][r] = vh.z; As_h[c4 + 3][r] = vh.w;
            As_l[c4 + 0][r] = vl.x; As_l[c4 + 1][r] = vl.y;
            As_l[c4 + 2][r] = vl.z; As_l[c4 + 3][r] = vl.w;
        }
#pragma unroll
        for (int l = 0; l < 2; l++) {
            int f  = t + l * 256;
            int r  = f >> 5;
            int c4 = (f & 31) * 4;
            *(uint4*)(&Bs_h[r][c4]) =
                *(const uint4*)(Bh + (long long)(k0 + r) * Nc + n0 + c4);
            *(uint4*)(&Bs_l[r][c4]) =
                *(const uint4*)(Bl + (long long)(k0 + r) * Nc + n0 + c4);
        }
        __syncthreads();

#pragma unroll
        for (int kb = 0; kb < 16; kb += 8) {
            uint32_t fah[4][4], fal[4][4], fbh[4][2], fbl[4][2];
#pragma unroll
            for (int mt = 0; mt < 4; mt++) {
                int mm = wm0 + mt * 16 + gid;
                fah[mt][0] = As_h[kb + tig    ][mm];
                fah[mt][1] = As_h[kb + tig    ][mm + 8];
                fah[mt][2] = As_h[kb + tig + 4][mm];
                fah[mt][3] = As_h[kb + tig + 4][mm + 8];
                fal[mt][0] = As_l[kb + tig    ][mm];
                fal[mt][1] = As_l[kb + tig    ][mm + 8];
                fal[mt][2] = As_l[kb + tig + 4][mm];
                fal[mt][3] = As_l[kb + tig + 4][mm + 8];
            }
#pragma unroll
            for (int nt = 0; nt < 4; nt++) {
                int nn = wn0 + nt * 8 + gid;
                fbh[nt][0] = Bs_h[kb + tig    ][nn];
                fbh[nt][1] = Bs_h[kb + tig + 4][nn];
                fbl[nt][0] = Bs_l[kb + tig    ][nn];
                fbl[nt][1] = Bs_l[kb + tig + 4][nn];
            }
#pragma unroll
            for (int mt = 0; mt < 4; mt++)
#pragma unroll
                for (int nt = 0; nt < 4; nt++) {
                    asm volatile(
                        "mma.sync.aligned.m16n8k8.row.col.f32.tf32.tf32.f32 "
                        "{%0,%1,%2,%3}, {%4,%5,%6,%7}, {%8,%9}, {%0,%1,%2,%3};"
                        : "+f"(acc[mt][nt][0]), "+f"(acc[mt][nt][1]),
                          "+f"(acc[mt][nt][2]), "+f"(acc[mt][nt][3])
                        : "r"(fah[mt][0]), "r"(fah[mt][1]), "r"(fah[mt][2]), "r"(fah[mt][3]),
                          "r"(fbl[nt][0]), "r"(fbl[nt][1]));
                    asm volatile(
                        "mma.sync.aligned.m16n8k8.row.col.f32.tf32.tf32.f32 "
                        "{%0,%1,%2,%3}, {%4,%5,%6,%7}, {%8,%9}, {%0,%1,%2,%3};"
                        : "+f"(acc[mt][nt][0]), "+f"(acc[mt][nt][1]),
                          "+f"(acc[mt][nt][2]), "+f"(acc[mt][nt][3])
                        : "r"(fal[mt][0]), "r"(fal[mt][1]), "r"(fal[mt][2]), "r"(fal[mt][3]),
                          "r"(fbh[nt][0]), "r"(fbh[nt][1]));
                    asm volatile(
                        "mma.sync.aligned.m16n8k8.row.col.f32.tf32.tf32.f32 "
                        "{%0,%1,%2,%3}, {%4,%5,%6,%7}, {%8,%9}, {%0,%1,%2,%3};"
                        : "+f"(acc[mt][nt][0]), "+f"(acc[mt][nt][1]),
                          "+f"(acc[mt][nt][2]), "+f"(acc[mt][nt][3])
                        : "r"(fah[mt][0]), "r"(fah[mt][1]), "r"(fah[mt][2]), "r"(fah[mt][3]),
                          "r"(fbh[nt][0]), "r"(fbh[nt][1]));
                }
        }
        __syncthreads();
    }

#pragma unroll
    for (int mt = 0; mt < 4; mt++) {
#pragma unroll
        for (int nt = 0; nt < 4; nt++) {
            int row = m0 + wm0 + mt * 16 + gid;
            int col = n0 + wn0 + nt * 8 + 2 * tig;
            float b0 = bias[col], b1 = bias[col + 1];
            float c0 = acc[mt][nt][0] + b0;
            float c1 = acc[mt][nt][1] + b1;
            float c2 = acc[mt][nt][2] + b0;
            float c3 = acc[mt][nt][3] + b1;
            if (HAS_RESID) {
                float2 r0 = *(const float2*)(resid + (long long)row * Nc + col);
                float2 r1 = *(const float2*)(resid + (long long)(row + 8) * Nc + col);
                c0 += r0.x; c1 += r0.y; c2 += r1.x; c3 += r1.y;
            }
            *(float2*)(C + (long long)row * Nc + col)       = make_float2(c0, c1);
            *(float2*)(C + (long long)(row + 8) * Nc + col) = make_float2(c2, c3);
        }
    }
}

// ---------------- weight packing: fp32 [K][Nc] -> bf16 k-pair u32 [K/2][Nc] --
__global__ void __launch_bounds__(256) packw_kernel(
    const float* __restrict__ W, uint32_t* __restrict__ P, int Nc,
    long long sW, long long sP)
{
    int n  = blockIdx.x * 256 + threadIdx.x;
    int k2 = blockIdx.y;
    int z  = blockIdx.z;
    const float* w = W + (long long)z * sW + (long long)(2 * k2) * Nc + n;
    P[(long long)z * sP + (long long)k2 * Nc + n] = packbf2(w[0], w[Nc]);
}

// ---------------- bf16 expert GEMM: block 128x256, warp 64x64, k32 ----------
// C = op(A[M,K](bf16) @ Bp(packed bf16 pairs [K/2][Nc]) + bias)
constexpr int EXP_SMEM = 2 * 16 * 136 * 4 + 2 * 16 * 264 * 4;  // 51200 B

template<int RELU, int OUTBF>
__global__ void __launch_bounds__(256) gemm_bf16w_kernel(
    const uint16_t* __restrict__ A, const uint32_t* __restrict__ Bp,
    const float* __restrict__ bias, void* __restrict__ Cout,
    int M, int Nc, int K,
    long long sA, long long sB, long long sBias, long long sC)
{
    extern __shared__ uint32_t dyn[];
    uint32_t* As = dyn;                    // [2][16][136]
    uint32_t* Bs = dyn + 2 * 16 * 136;     // [2][16][264]

    int z = blockIdx.z;
    A    += (long long)z * sA;
    Bp   += (long long)z * sB;
    bias += (long long)z * sBias;

    int t    = threadIdx.x;
    int wid  = t >> 5, lane = t & 31;
    int gid  = lane >> 2, tig = lane & 3;
    int wm0  = (wid & 1) * 64;
    int wn0  = (wid >> 1) * 64;            // 4 n-warps * 64
    int m0   = blockIdx.y * 128, n0 = blockIdx.x * 256;

    int am  = t & 127, ahh = t >> 7;       // A: row am, octet ahh and ahh+2
    int bk  = t >> 4,  bn  = (t & 15) * 16;

    float acc[4][8][4];
#pragma unroll
    for (int mt = 0; mt < 4; mt++)
#pragma unroll
        for (int nt = 0; nt < 8; nt++)
#pragma unroll
            for (int r = 0; r < 4; r++) acc[mt][nt][r] = 0.f;

    auto stageA = [&](int buf, uint4 va0, uint4 va1) {
        uint32_t* as = As + buf * (16 * 136);
        as[(ahh * 4 + 0) * 136 + am] = va0.x;
        as[(ahh * 4 + 1) * 136 + am] = va0.y;
        as[(ahh * 4 + 2) * 136 + am] = va0.z;
        as[(ahh * 4 + 3) * 136 + am] = va0.w;
        as[((ahh + 2) * 4 + 0) * 136 + am] = va1.x;
        as[((ahh + 2) * 4 + 1) * 136 + am] = va1.y;
        as[((ahh + 2) * 4 + 2) * 136 + am] = va1.z;
        as[((ahh + 2) * 4 + 3) * 136 + am] = va1.w;
    };
    auto stageB = [&](int buf, const uint4* vb) {
        uint32_t* bs = Bs + buf * (16 * 264);
#pragma unroll
        for (int j = 0; j < 4; j++)
            *(uint4*)&bs[bk * 264 + bn + j * 4] = vb[j];
    };

    const int nIter = K / 32;
    {   // stage tile 0
        uint4 va0 = *(const uint4*)(A + (long long)(m0 + am) * K + ahh * 8);
        uint4 va1 = *(const uint4*)(A + (long long)(m0 + am) * K + (ahh + 2) * 8);
        uint4 vb[4];
#pragma unroll
        for (int j = 0; j < 4; j++)
            vb[j] = *(const uint4*)(Bp + (long long)bk * Nc + n0 + bn + j * 4);
        stageA(0, va0, va1);
        stageB(0, vb);
    }
    __syncthreads();

    for (int it = 0; it < nIter; ++it) {
        int cur = it & 1;
        uint4 va0, va1, vb[4];
        bool pf = (it + 1 < nIter);
        if (pf) {
            long long ka = (long long)(m0 + am) * K + (it + 1) * 32;
            va0 = *(const uint4*)(A + ka + ahh * 8);
            va1 = *(const uint4*)(A + ka + (ahh + 2) * 8);
            long long kb = (long long)(it + 1) * 16 + bk;
#pragma unroll
            for (int j = 0; j < 4; j++)
                vb[j] = *(const uint4*)(Bp + kb * Nc + n0 + bn + j * 4);
        }
        const uint32_t* as = As + cur * (16 * 136);
        const uint32_t* bs = Bs + cur * (16 * 264);
#pragma unroll
        for (int kb2 = 0; kb2 < 2; kb2++) {
            int ko = kb2 * 8;
            uint32_t af[4][4], bfr[8][2];
#pragma unroll
            for (int mt = 0; mt < 4; mt++) {
                int mm = wm0 + mt * 16 + gid;
                af[mt][0] = as[(ko + tig    ) * 136 + mm];
                af[mt][1] = as[(ko + tig    ) * 136 + mm + 8];
                af[mt][2] = as[(ko + tig + 4) * 136 + mm];
                af[mt][3] = as[(ko + tig + 4) * 136 + mm + 8];
            }
#pragma unroll
            for (int nt = 0; nt < 8; nt++) {
                int nn = wn0 + nt * 8 + gid;
                bfr[nt][0] = bs[(ko + tig    ) * 264 + nn];
                bfr[nt][1] = bs[(ko + tig + 4) * 264 + nn];
            }
#pragma unroll
            for (int mt = 0; mt < 4; mt++)
#pragma unroll
                for (int nt = 0; nt < 8; nt++) {
                    asm volatile(
                        "mma.sync.aligned.m16n8k16.row.col.f32.bf16.bf16.f32 "
                        "{%0,%1,%2,%3}, {%4,%5,%6,%7}, {%8,%9}, {%0,%1,%2,%3};"
                        : "+f"(acc[mt][nt][0]), "+f"(acc[mt][nt][1]),
                          "+f"(acc[mt][nt][2]), "+f"(acc[mt][nt][3])
                        : "r"(af[mt][0]), "r"(af[mt][1]),
                          "r"(af[mt][2]), "r"(af[mt][3]),
                          "r"(bfr[nt][0]), "r"(bfr[nt][1]));
                }
        }
        if (pf) {
            stageA(cur ^ 1, va0, va1);
            stageB(cur ^ 1, vb);
        }
        __syncthreads();
    }

#pragma unroll
    for (int mt = 0; mt < 4; mt++) {
#pragma unroll
        for (int nt = 0; nt < 8; nt++) {
            int row = m0 + wm0 + mt * 16 + gid;
            int col = n0 + wn0 + nt * 8 + 2 * tig;
            float b0 = bias[col], b1 = bias[col + 1];
            float c0 = acc[mt][nt][0] + b0;
            float c1 = acc[mt][nt][1] + b1;
            float c2 = acc[mt][nt][2] + b0;
            float c3 = acc[mt][nt][3] + b1;
            if (RELU) {
                c0 = fmaxf(c0, 0.f); c1 = fmaxf(c1, 0.f);
                c2 = fmaxf(c2, 0.f); c3 = fmaxf(c3, 0.f);
            }
            if (OUTBF) {
                uint16_t* Cb = (uint16_t*)Cout + (long long)z * sC;
                *(uint32_t*)(Cb + (long long)row * Nc + col)       = packbf2(c0, c1);
                *(uint32_t*)(Cb + (long long)(row + 8) * Nc + col) = packbf2(c2, c3);
            } else {
                float* Cf = (float*)Cout + (long long)z * sC;
                *(float2*)(Cf + (long long)row * Nc + col)       = make_float2(c0, c1);
                *(float2*)(Cf + (long long)(row + 8) * Nc + col) = make_float2(c2, c3);
            }
        }
    }
}

// ---------------- flash attention (fp32, causal; strided qkv input) ---------
constexpr int QT = 128, KT = 64;
constexpr int ATTN_SMEM = (QT * (HD + 1) + 2 * KT * HD) * 4;  // 66048 B

__global__ void __launch_bounds__(128) attn_kernel(
    const float* __restrict__ Q, const float* __restrict__ Kg,
    const float* __restrict__ Vg, int LD,
    uint32_t* __restrict__ Oh, uint32_t* __restrict__ Ol)
{
    extern __shared__ float sm[];
    float* q_s = sm;
    float* k_s = sm + QT * (HD + 1);
    float* v_s = k_s + KT * HD;

    int bh = blockIdx.y;
    int h  = bh % H, b = bh / H;
    int q0 = blockIdx.x * QT;
    int t  = threadIdx.x;
    long base = (long)b * LD + (long)h * HD;
    long rs   = (long)B * LD;    // row stride per s

    for (int f = t; f < QT * HD / 4; f += 128) {
        int r  = f / (HD / 4);
        int c4 = (f % (HD / 4)) * 4;
        float4 v = *(const float4*)(Q + (long)(q0 + r) * rs + base + c4);
        q_s[r * (HD + 1) + c4 + 0] = v.x;
        q_s[r * (HD + 1) + c4 + 1] = v.y;
        q_s[r * (HD + 1) + c4 + 2] = v.z;
        q_s[r * (HD + 1) + c4 + 3] = v.w;
    }
    __syncthreads();

    int sq = q0 + t;
    float m_run = -1e30f, l_run = 0.f;
    float acc[HD];
#pragma unroll
    for (int d = 0; d < HD; d++) acc[d] = 0.f;

    int kend = q0 + QT;
    for (int k0 = 0; k0 < kend; k0 += KT) {
        for (int f = t; f < KT * HD / 4; f += 128) {
            int r  = f / (HD / 4);
            int c4 = (f % (HD / 4)) * 4;
            *(float4*)(&k_s[r * HD + c4]) =
                *(const float4*)(Kg + (long)(k0 + r) * rs + base + c4);
            *(float4*)(&v_s[r * HD + c4]) =
                *(const float4*)(Vg + (long)(k0 + r) * rs + base + c4);
        }
        __syncthreads();

        float s[KT];
#pragma unroll
        for (int j = 0; j < KT; j++) s[j] = 0.f;
        for (int d = 0; d < HD; d++) {
            float qd = q_s[t * (HD + 1) + d];
#pragma unroll
            for (int j = 0; j < KT; j++) s[j] += qd * k_s[j * HD + d];
        }
        float mnew = m_run;
#pragma unroll
        for (int j = 0; j < KT; j++) {
            if (k0 + j > sq) s[j] = -1e9f;
            mnew = fmaxf(mnew, s[j]);
        }
        float corr = __expf(m_run - mnew);
        l_run *= corr;
#pragma unroll
        for (int d = 0; d < HD; d++) acc[d] *= corr;
        for (int j = 0; j < KT; j++) {
            float p = __expf(s[j] - mnew);
            l_run += p;
#pragma unroll
            for (int d = 0; d < HD; d++) acc[d] += p * v_s[j * HD + d];
        }
        m_run = mnew;
        __syncthreads();
    }
    float inv = 1.f / l_run;
    long off = (long)sq * (B * D) + (long)b * D + (long)h * HD;
#pragma unroll
    for (int d = 0; d < HD; d++) {
        float v = acc[d] * inv;
        uint32_t hi = f2tf32(v);
        Oh[off + d] = hi;
        Ol[off + d] = f2tf32(v - __uint_as_float(hi));
    }
}

// ---------------- gate: logits, softmax, argmax (fp32, exact) ----------------
__global__ void __launch_bounds__(256) gate_kernel(
    const float* __restrict__ tok, const float* __restrict__ gw,
    float* __restrict__ gates, int* __restrict__ eidx, float* __restrict__ gp)
{
    int n = blockIdx.x, t = threadIdx.x;
    const float* row = tok + (long)n * D;
    float p[E];
#pragma unroll
    for (int e = 0; e < E; e++) p[e] = 0.f;
    for (int d = t; d < D; d += 256) {
        float xv = row[d];
        const float* w = gw + (long)d * E;
#pragma unroll
        for (int e = 0; e < E; e++) p[e] += xv * w[e];
    }
    __shared__ float red[256 * E];
#pragma unroll
    for (int e = 0; e < E; e++) red[t * E + e] = p[e];
    __syncthreads();
    for (int st = 128; st > 0; st >>= 1) {
        if (t < st)
#pragma unroll
            for (int e = 0; e < E; e++) red[t * E + e] += red[(t + st) * E + e];
        __syncthreads();
    }
    if (t == 0) {
        float lg[E], mx = -1e30f;
#pragma unroll
        for (int e = 0; e < E; e++) { lg[e] = red[e]; mx = fmaxf(mx, lg[e]); }
        float sum = 0.f, pr[E];
#pragma unroll
        for (int e = 0; e < E; e++) { pr[e] = __expf(lg[e] - mx); sum += pr[e]; }
        float inv = 1.f / sum;
        int best = 0; float bv = -1e30f;
#pragma unroll
        for (int e = 0; e < E; e++) {
            float g = pr[e] * inv;
            gates[(long)n * E + e] = g;
            if (g > bv) { bv = g; best = e; }
        }
        eidx[n] = best;
        gp[n]   = bv;
    }
}

// ---------------- routing scan (deterministic, single block) ----------------
__global__ void __launch_bounds__(256) scan_kernel(
    const int* __restrict__ eidx, const float* __restrict__ gp,
    int* __restrict__ slot, float* __restrict__ gv, int* __restrict__ cnt)
{
    __shared__ int scnt[256][E];
    int t = threadIdx.x;
    int c[E];
#pragma unroll
    for (int e = 0; e < E; e++) c[e] = 0;
    int n0 = t * (N / 256);
    for (int i = 0; i < N / 256; i++) c[eidx[n0 + i]]++;
#pragma unroll
    for (int e = 0; e < E; e++) scnt[t][e] = c[e];
    __syncthreads();
    if (t < E) {
        int run = 0;
        for (int j = 0; j < 256; j++) { int tmp = scnt[j][t]; scnt[j][t] = run; run += tmp; }
        cnt[t] = run;
    }
    __syncthreads();
    int off[E];
#pragma unroll
    for (int e = 0; e < E; e++) off[e] = scnt[t][e];
    for (int i = 0; i < N / 256; i++) {
        int n = n0 + i;
        int e = eidx[n];
        int l = off[e]++;
        bool keep = (l < CAP);
        slot[n] = keep ? e * CAP + l : -1;
        gv[n]   = keep ? gp[n] : 0.f;
    }
}

// ---------------- l_aux (deterministic tree reduce) ----------------
__global__ void __launch_bounds__(256) laux_kernel(
    const float* __restrict__ gates, const int* __restrict__ cnt,
    float* __restrict__ out_laux)
{
    __shared__ float red[256];
    int t = threadIdx.x;
    float loc[E];
#pragma unroll
    for (int e = 0; e < E; e++) loc[e] = 0.f;
    for (int n = t; n < N; n += 256)
#pragma unroll
        for (int e = 0; e < E; e++) loc[e] += gates[(long)n * E + e];
    float total[E];
    for (int e = 0; e < E; e++) {
        red[t] = loc[e]; __syncthreads();
        for (int st = 128; st > 0; st >>= 1) {
            if (t < st) red[t] += red[t + st];
            __syncthreads();
        }
        if (t == 0) total[e] = red[0];
        __syncthreads();
    }
    if (t == 0) {
        float la = 0.f;
        for (int e = 0; e < E; e++)
            la += (total[e] / N) * ((float)cnt[e] / N);
        *out_laux = (float)E * la;
    }
}

// ---------------- dispatch / combine ----------------
__global__ void __launch_bounds__(256) dispatch_kernel(
    const float* __restrict__ tok, const int* __restrict__ slot,
    uint16_t* __restrict__ dispb)
{
    int n = blockIdx.x;
    int s = slot[n];
    if (s < 0) return;
    int t = threadIdx.x;
    float4 v = ((const float4*)(tok + (long)n * D))[t];
    uint2 o;
    o.x = packbf2(v.x, v.y);
    o.y = packbf2(v.z, v.w);
    *(uint2*)(dispb + (long)s * D + t * 4) = o;
}

__global__ void __launch_bounds__(256) combine_kernel(
    const float* __restrict__ x1, const float* __restrict__ eo,
    const int* __restrict__ slot, const float* __restrict__ gv,
    float* __restrict__ out)
{
    int n = blockIdx.x, t = threadIdx.x;
    int s = slot[n];
    float g = gv[n];
    float4 r = ((const float4*)(x1 + (long)n * D))[t];
    if (s >= 0) {
        float4 v = ((const float4*)(eo + (long)s * D))[t];
        r.x += v.x * g; r.y += v.y * g; r.z += v.z * g; r.w += v.w * g;
    }
    ((float4*)(out + (long)n * D))[t] = r;
}

// ---------------- launch ----------------
extern "C" void kernel_launch(void* const* d_in, const int* in_sizes, int n_in,
                              void* d_out, int out_size) {
    const float* x    = (const float*)d_in[0];
    const float* wq   = (const float*)d_in[2];
    const float* bq   = (const float*)d_in[3];
    const float* wk   = (const float*)d_in[4];
    const float* bk   = (const float*)d_in[5];
    const float* wv   = (const float*)d_in[6];
    const float* bv   = (const float*)d_in[7];
    const float* wo   = (const float*)d_in[8];
    const float* bo   = (const float*)d_in[9];
    const float* ln1g = (const float*)d_in[10];
    const float* ln1b = (const float*)d_in[11];
    const float* ln2g = (const float*)d_in[12];
    const float* ln2b = (const float*)d_in[13];
    const float* gw   = (const float*)d_in[14];
    const float* w1   = (const float*)d_in[15];
    const float* b1   = (const float*)d_in[16];
    const float* w2   = (const float*)d_in[17];
    const float* b2   = (const float*)d_in[18];
    float* out = (float*)d_out;

    float *qkv, *x1, *tok, *eo, *gates, *gp, *gv, *b3;
    uint32_t *xnh, *xnl, *aoh, *aol, *wqkvh, *wqkvl, *woh, *wol, *w1p, *w2p;
    uint16_t *dispb, *hb;
    int *eidx, *slot, *cnt;
    cudaGetSymbolAddress((void**)&xnh,   g_xnh);
    cudaGetSymbolAddress((void**)&xnl,   g_xnl);
    cudaGetSymbolAddress((void**)&qkv,   g_qkv);
    cudaGetSymbolAddress((void**)&aoh,   g_aoh);
    cudaGetSymbolAddress((void**)&aol,   g_aol);
    cudaGetSymbolAddress((void**)&x1,    g_x1);
    cudaGetSymbolAddress((void**)&tok,   g_tok);
    cudaGetSymbolAddress((void**)&wqkvh, g_wqkvh);
    cudaGetSymbolAddress((void**)&wqkvl, g_wqkvl);
    cudaGetSymbolAddress((void**)&b3,    g_b3);
    cudaGetSymbolAddress((void**)&woh,   g_woh);
    cudaGetSymbolAddress((void**)&wol,   g_wol);
    cudaGetSymbolAddress((void**)&dispb, g_dispb);
    cudaGetSymbolAddress((void**)&hb,    g_hb);
    cudaGetSymbolAddress((void**)&eo,    g_eo);
    cudaGetSymbolAddress((void**)&w1p,   g_w1p);
    cudaGetSymbolAddress((void**)&w2p,   g_w2p);
    cudaGetSymbolAddress((void**)&gates, g_gates);
    cudaGetSymbolAddress((void**)&gp,    g_gp);
    cudaGetSymbolAddress((void**)&gv,    g_gv);
    cudaGetSymbolAddress((void**)&eidx,  g_eidx);
    cudaGetSymbolAddress((void**)&slot,  g_slot);
    cudaGetSymbolAddress((void**)&cnt,   g_cnt);

    cudaFuncSetAttribute(attn_kernel,
                         cudaFuncAttributeMaxDynamicSharedMemorySize, ATTN_SMEM);
    cudaFuncSetAttribute(gemm_bf16w_kernel<1, 1>,
                         cudaFuncAttributeMaxDynamicSharedMemorySize, EXP_SMEM);
    cudaFuncSetAttribute(gemm_bf16w_kernel<0, 0>,
                         cudaFuncAttributeMaxDynamicSharedMemorySize, EXP_SMEM);

    // one-time prep: merged qkv weight split (q scaled by 1/8 exactly),
    // bias concat, wo split, expert weight k-pair packs
    splitw3_kernel<<<D * D / 256, 256>>>(wq, wqkvh, wqkvl, 0,     0.125f);
    splitw3_kernel<<<D * D / 256, 256>>>(wk, wqkvh, wqkvl, D,     1.0f);
    splitw3_kernel<<<D * D / 256, 256>>>(wv, wqkvh, wqkvl, 2 * D, 1.0f);
    biascat_kernel<<<D / 256, 256>>>(bq, b3,         0.125f);
    biascat_kernel<<<D / 256, 256>>>(bk, b3 + D,     1.0f);
    biascat_kernel<<<D / 256, 256>>>(bv, b3 + 2 * D, 1.0f);
    splitw_kernel<<<D * D / 256, 256>>>(wo, woh, wol);
    packw_kernel<<<dim3(F / 256, D / 2, E), 256>>>(w1, w1p, F,
        (long long)D * F, (long long)(D / 2) * F);
    packw_kernel<<<dim3(D / 256, F / 2, E), 256>>>(w2, w2p, D,
        (long long)F * D, (long long)(F / 2) * D);

    // 1) LN1 -> tf32 hi/lo
    ln_split_kernel<<<N, 256>>>(x, ln1g, ln1b, xnh, xnl);
    // 2) merged QKV projection (3xTF32, Nc=3072)
    gemm_t3s_kernel<0><<<dim3(D3 / 128, N / 128), 256>>>(
        xnh, xnl, wqkvh, wqkvl, b3, nullptr, qkv, N, D3, D);
    // 3) attention (reads strided qkv)
    attn_kernel<<<dim3(S / QT, B * H), 128, ATTN_SMEM>>>(
        qkv, qkv + D, qkv + 2 * D, D3, aoh, aol);
    // 4) output projection + residual
    gemm_t3s_kernel<1><<<dim3(D / 128, N / 128), 256>>>(
        aoh, aol, woh, wol, bo, x, x1, N, D, D);
    // 5) LN2
    ln_kernel<<<N, 256>>>(x1, ln2g, ln2b, tok);
    // 6) gate
    gate_kernel<<<N, 256>>>(tok, gw, gates, eidx, gp);
    // 7) routing scan
    scan_kernel<<<1, 256>>>(eidx, gp, slot, gv, cnt);
    // 8) l_aux -> last output element
    laux_kernel<<<1, 256>>>(gates, cnt, out + (out_size - 1));
    // 9) dispatch (writes bf16)
    dispatch_kernel<<<N, 256>>>(tok, slot, dispb);
    // 10) expert GEMM1 (relu, bf16 -> bf16)
    gemm_bf16w_kernel<1, 1><<<dim3(F / 256, CAP / 128, E), 256, EXP_SMEM>>>(
        dispb, w1p, b1, hb, CAP, F, D,
        (long long)CAP * D, (long long)(D / 2) * F, (long long)F, (long long)CAP * F);
    // 11) expert GEMM2 (bf16 -> fp32)
    gemm_bf16w_kernel<0, 0><<<dim3(D / 256, CAP / 128, E), 256, EXP_SMEM>>>(
        hb, w2p, b2, eo, CAP, D, F,
        (long long)CAP * F, (long long)(F / 2) * D, (long long)D, (long long)CAP * D);
    // 12) combine + residual -> output
    combine_kernel<<<N, 256>>>(x1, eo, slot, gv, out);
}